// round 1
// baseline (speedup 1.0000x reference)
#include <cuda_runtime.h>

#define N_NODES 100000
#define D 64
#define E_MAX 1600000
#define ROWS 16

// ---------------- device scratch (no allocations allowed) ----------------
__device__ float g_P[N_NODES * D];     // relu(fc_pool(h)) per node
__device__ float g_AGG[N_NODES * D];   // max-pool aggregation
__device__ float g_H1[N_NODES * D];    // layer-1 output
__device__ int   g_deg[N_NODES + 1];
__device__ int   g_off[N_NODES + 1];
__device__ int   g_cur[N_NODES];
__device__ int   g_csr[E_MAX];         // src node per edge, grouped by dst

// ---------------- CSR build ----------------
__global__ void zero_deg_kernel() {
    int i = blockIdx.x * blockDim.x + threadIdx.x;
    if (i <= N_NODES) g_deg[i] = 0;
}

__global__ void count_deg_kernel(const int* __restrict__ dst, int E) {
    int i = blockIdx.x * blockDim.x + threadIdx.x;
    if (i < E) atomicAdd(&g_deg[dst[i]], 1);
}

// single-block exclusive scan over 100001 entries; also seeds the cursor
__global__ void scan_deg_kernel() {
    __shared__ int sums[1024];
    int tid = threadIdx.x;
    const int chunk = (N_NODES + 1023) / 1024;
    int start = tid * chunk;
    int end = min(start + chunk, N_NODES);
    int s = 0;
    for (int i = start; i < end; i++) s += g_deg[i];
    sums[tid] = s;
    __syncthreads();
    // Hillis-Steele inclusive scan
    for (int off = 1; off < 1024; off <<= 1) {
        int v = (tid >= off) ? sums[tid - off] : 0;
        __syncthreads();
        sums[tid] += v;
        __syncthreads();
    }
    int run = (tid > 0) ? sums[tid - 1] : 0;
    for (int i = start; i < end; i++) {
        g_off[i] = run;
        g_cur[i] = run;
        run += g_deg[i];
    }
    if (tid == 1023) g_off[N_NODES] = run;
}

__global__ void fill_csr_kernel(const int* __restrict__ src,
                                const int* __restrict__ dst, int E) {
    int i = blockIdx.x * blockDim.x + threadIdx.x;
    if (i < E) {
        int p = atomicAdd(&g_cur[dst[i]], 1);
        g_csr[p] = src[i];
    }
}

// ---------------- fc_pool: P = relu(X @ W + b), per node ----------------
__global__ void fc_relu_kernel(const float* __restrict__ X, int use_h1,
                               const float* __restrict__ W,
                               const float* __restrict__ b) {
    __shared__ float Ws[D][D];
    __shared__ float xs[ROWS][D];
    __shared__ float bs[D];
    const float* Xp = use_h1 ? g_H1 : X;
    int tid = threadIdx.x;  // 256 threads
    for (int i = tid; i < D * D; i += 256) Ws[i / D][i % D] = W[i];
    if (tid < D) bs[tid] = b[tid];
    int row0 = blockIdx.x * ROWS;
    for (int i = tid; i < ROWS * D; i += 256) {
        int r = i / D, c = i % D;
        int gr = row0 + r;
        xs[r][c] = (gr < N_NODES) ? Xp[gr * D + c] : 0.f;
    }
    __syncthreads();
    int c = tid & 63, r0 = tid >> 6;
    for (int r = r0; r < ROWS; r += 4) {
        float acc = bs[c];
        #pragma unroll
        for (int k = 0; k < D; k++) acc += xs[r][k] * Ws[k][c];
        int gr = row0 + r;
        if (gr < N_NODES) g_P[gr * D + c] = fmaxf(acc, 0.f);
    }
}

// ---------------- max-pool aggregation: warp per dst node ----------------
__global__ void aggregate_kernel() {
    int node = blockIdx.x * (blockDim.x >> 5) + (threadIdx.x >> 5);
    if (node >= N_NODES) return;
    int lane = threadIdx.x & 31;
    int beg = g_off[node];
    int end = g_off[node + 1];
    float2 m = make_float2(0.f, 0.f);  // relu >= 0, so 0-init == DGL's zero-fill
    for (int i = beg; i < end; i++) {
        int s = g_csr[i];
        float2 v = *reinterpret_cast<const float2*>(&g_P[s * D + lane * 2]);
        m.x = fmaxf(m.x, v.x);
        m.y = fmaxf(m.y, v.y);
    }
    *reinterpret_cast<float2*>(&g_AGG[node * D + lane * 2]) = m;
}

// ---------------- combine: out = act(X@Wself + AGG@Wneigh + bias) ----------
template <bool TANH>
__global__ void combine_kernel(const float* __restrict__ X, int use_h1,
                               const float* __restrict__ Wself,
                               const float* __restrict__ Wneigh,
                               const float* __restrict__ bias,
                               float* __restrict__ out, int out_is_h1) {
    __shared__ float Ws[D][D];
    __shared__ float Wn[D][D];
    __shared__ float xs[ROWS][D];
    __shared__ float as[ROWS][D];
    __shared__ float bs[D];
    const float* Xp = use_h1 ? g_H1 : X;
    float* Op = out_is_h1 ? g_H1 : out;
    int tid = threadIdx.x;  // 256
    for (int i = tid; i < D * D; i += 256) {
        Ws[i / D][i % D] = Wself[i];
        Wn[i / D][i % D] = Wneigh[i];
    }
    if (tid < D) bs[tid] = bias[tid];
    int row0 = blockIdx.x * ROWS;
    for (int i = tid; i < ROWS * D; i += 256) {
        int r = i / D, c = i % D;
        int gr = row0 + r;
        xs[r][c] = (gr < N_NODES) ? Xp[gr * D + c] : 0.f;
        as[r][c] = (gr < N_NODES) ? g_AGG[gr * D + c] : 0.f;
    }
    __syncthreads();
    int c = tid & 63, r0 = tid >> 6;
    for (int r = r0; r < ROWS; r += 4) {
        float acc = bs[c];
        #pragma unroll
        for (int k = 0; k < D; k++) acc += xs[r][k] * Ws[k][c];
        #pragma unroll
        for (int k = 0; k < D; k++) acc += as[r][k] * Wn[k][c];
        int gr = row0 + r;
        if (gr < N_NODES) Op[gr * D + c] = TANH ? tanhf(acc) : acc;
    }
}

// ---------------- launch ----------------
extern "C" void kernel_launch(void* const* d_in, const int* in_sizes, int n_in,
                              void* d_out, int out_size) {
    const float* x    = (const float*)d_in[0];
    const int*   esrc = (const int*)d_in[1];
    const int*   edst = (const int*)d_in[2];
    const float* Wp1  = (const float*)d_in[3];
    const float* bp1  = (const float*)d_in[4];
    const float* Ws1  = (const float*)d_in[5];
    const float* Wn1  = (const float*)d_in[6];
    const float* b1   = (const float*)d_in[7];
    const float* Wp2  = (const float*)d_in[8];
    const float* bp2  = (const float*)d_in[9];
    const float* Ws2  = (const float*)d_in[10];
    const float* Wn2  = (const float*)d_in[11];
    const float* b2   = (const float*)d_in[12];
    float* out = (float*)d_out;

    int E = in_sizes[1];
    if (E > E_MAX) E = E_MAX;

    const int eb = (E + 255) / 256;
    const int nb_nodes = (N_NODES + 255 + 1) / 256;  // covers N_NODES+1
    const int fc_blocks = (N_NODES + ROWS - 1) / ROWS;
    const int agg_blocks = (N_NODES + 7) / 8;  // 8 warps/block, warp per node

    // CSR build (shared by both layers)
    zero_deg_kernel<<<nb_nodes, 256>>>();
    count_deg_kernel<<<eb, 256>>>(edst, E);
    scan_deg_kernel<<<1, 1024>>>();
    fill_csr_kernel<<<eb, 256>>>(esrc, edst, E);

    // layer 1
    fc_relu_kernel<<<fc_blocks, 256>>>(x, 0, Wp1, bp1);
    aggregate_kernel<<<agg_blocks, 256>>>();
    combine_kernel<true><<<fc_blocks, 256>>>(x, 0, Ws1, Wn1, b1, nullptr, 1);

    // layer 2
    fc_relu_kernel<<<fc_blocks, 256>>>(nullptr, 1, Wp2, bp2);
    aggregate_kernel<<<agg_blocks, 256>>>();
    combine_kernel<false><<<fc_blocks, 256>>>(nullptr, 1, Ws2, Wn2, b2, out, 0);
}

// round 5
// speedup vs baseline: 2.0047x; 2.0047x over previous
#include <cuda_runtime.h>

#define N_NODES 100000
#define D 64
#define E_MAX 1600000

// ---------------- device scratch (no allocations allowed) ----------------
__device__ float g_P[N_NODES * D];     // relu(fc_pool(h)) per node
__device__ float g_AGG[N_NODES * D];   // max-pool aggregation
__device__ float g_H1[N_NODES * D];    // layer-1 output
__device__ int   g_deg[N_NODES + 1];
__device__ int   g_off[N_NODES + 1];
__device__ int   g_cur[N_NODES];
__device__ int   g_csr[E_MAX];         // src node per edge, grouped by dst

// ---------------- CSR build ----------------
__global__ void zero_deg_kernel() {
    int i = blockIdx.x * blockDim.x + threadIdx.x;
    if (i <= N_NODES) g_deg[i] = 0;
}

__global__ void count_deg_kernel(const int* __restrict__ dst, int E) {
    int i = blockIdx.x * blockDim.x + threadIdx.x;
    if (i < E) atomicAdd(&g_deg[dst[i]], 1);
}

// single-block exclusive scan over 100001 entries; also seeds the cursor
__global__ void scan_deg_kernel() {
    __shared__ int sums[1024];
    int tid = threadIdx.x;
    const int chunk = (N_NODES + 1023) / 1024;
    int start = tid * chunk;
    int end = min(start + chunk, N_NODES);
    int s = 0;
    for (int i = start; i < end; i++) s += g_deg[i];
    sums[tid] = s;
    __syncthreads();
    for (int off = 1; off < 1024; off <<= 1) {
        int v = (tid >= off) ? sums[tid - off] : 0;
        __syncthreads();
        sums[tid] += v;
        __syncthreads();
    }
    int run = (tid > 0) ? sums[tid - 1] : 0;
    for (int i = start; i < end; i++) {
        g_off[i] = run;
        g_cur[i] = run;
        run += g_deg[i];
    }
    if (tid == 1023) g_off[N_NODES] = run;
}

__global__ void fill_csr_kernel(const int* __restrict__ src,
                                const int* __restrict__ dst, int E) {
    int i = blockIdx.x * blockDim.x + threadIdx.x;
    if (i < E) {
        int p = atomicAdd(&g_cur[dst[i]], 1);
        g_csr[p] = src[i];
    }
}

// ---------------- register-tiled GEMM machinery ----------------
// Block: 256 threads, tile = 64 rows x 64 cols, thread = 4x4 micro-tile held
// in four named float4s. Device globals are referenced ONLY from device code
// (selected by template flags) — never passed as kernel args from host.

__device__ __forceinline__ void load_tileT(float* __restrict__ AT,
                                           const float* __restrict__ src,
                                           int row0) {
    int tid = threadIdx.x;
    #pragma unroll
    for (int i = 0; i < 4; i++) {
        int idx = i * 256 + tid;          // 0..1023 float4 slots
        int r = idx & 63;                  // row within tile
        int c4 = idx >> 6;                 // float4-column 0..15
        int gr = row0 + r;
        float4 v = make_float4(0.f, 0.f, 0.f, 0.f);
        if (gr < N_NODES) v = *reinterpret_cast<const float4*>(&src[gr * D + c4 * 4]);
        int k0 = c4 * 4;
        AT[(k0 + 0) * 64 + r] = v.x;
        AT[(k0 + 1) * 64 + r] = v.y;
        AT[(k0 + 2) * 64 + r] = v.z;
        AT[(k0 + 3) * 64 + r] = v.w;
    }
}

__device__ __forceinline__ void load_W(float* __restrict__ WS,
                                       const float* __restrict__ W) {
    int tid = threadIdx.x;
    float4* d = reinterpret_cast<float4*>(WS);
    const float4* s = reinterpret_cast<const float4*>(W);
    #pragma unroll
    for (int i = 0; i < 4; i++) d[i * 256 + tid] = s[i * 256 + tid];
}

// inner product loop over k: 2x LDS.128 feed 16 FMAs into named accumulators
#define GEMM_LOOP(ATbuf, WSbuf)                                                \
    _Pragma("unroll")                                                          \
    for (int k = 0; k < D; k++) {                                              \
        float4 a = *reinterpret_cast<const float4*>(&(ATbuf)[k * 64 + ty4]);   \
        float4 w = *reinterpret_cast<const float4*>(&(WSbuf)[k * 64 + tx4]);   \
        c0.x += a.x * w.x; c0.y += a.x * w.y; c0.z += a.x * w.z; c0.w += a.x * w.w; \
        c1.x += a.y * w.x; c1.y += a.y * w.y; c1.z += a.y * w.z; c1.w += a.y * w.w; \
        c2.x += a.z * w.x; c2.y += a.z * w.y; c2.z += a.z * w.z; c2.w += a.z * w.w; \
        c3.x += a.w * w.x; c3.y += a.w * w.y; c3.z += a.w * w.z; c3.w += a.w * w.w; \
    }

// ACT: 0 = relu, 1 = tanh, 2 = none
#define STORE_ROW(cr, roff, outp)                                              \
    {                                                                          \
        int gr = row0 + ty4 + (roff);                                          \
        if (gr < N_NODES) {                                                    \
            float v0 = cr.x + bx, v1 = cr.y + by, v2 = cr.z + bz, v3 = cr.w + bw; \
            if (ACT == 0) { v0 = fmaxf(v0, 0.f); v1 = fmaxf(v1, 0.f);          \
                            v2 = fmaxf(v2, 0.f); v3 = fmaxf(v3, 0.f); }        \
            if (ACT == 1) { v0 = tanhf(v0); v1 = tanhf(v1);                    \
                            v2 = tanhf(v2); v3 = tanhf(v3); }                  \
            float4 o; o.x = v0; o.y = v1; o.z = v2; o.w = v3;                  \
            *reinterpret_cast<float4*>(&(outp)[gr * D + tx4]) = o;             \
        }                                                                      \
    }

// P = relu(src @ W + b); src = X (layer 1) or g_H1 (layer 2); writes g_P
template <int ACT, int USE_H1>
__global__ __launch_bounds__(256) void fc_kernel(const float* __restrict__ X,
                                                 const float* __restrict__ W,
                                                 const float* __restrict__ b) {
    __shared__ float AT[64 * 64];
    __shared__ float WS[64 * 64];
    __shared__ float BS[64];
    int tid = threadIdx.x;
    int row0 = blockIdx.x * 64;
    int tx4 = (tid & 15) * 4;
    int ty4 = (tid >> 4) * 4;

    const float* src = USE_H1 ? (const float*)g_H1 : X;
    load_tileT(AT, src, row0);
    load_W(WS, W);
    if (tid < 64) BS[tid] = b[tid];
    __syncthreads();

    float4 c0 = make_float4(0.f, 0.f, 0.f, 0.f);
    float4 c1 = c0, c2 = c0, c3 = c0;
    GEMM_LOOP(AT, WS);

    float bx = BS[tx4 + 0], by = BS[tx4 + 1], bz = BS[tx4 + 2], bw = BS[tx4 + 3];
    float* outp = g_P;
    STORE_ROW(c0, 0, outp);
    STORE_ROW(c1, 1, outp);
    STORE_ROW(c2, 2, outp);
    STORE_ROW(c3, 3, outp);
}

// out = act(src@Wself + AGG@Wneigh + bias); src/out selected by flags
template <int ACT, int USE_H1, int OUT_IS_H1>
__global__ __launch_bounds__(256) void combine_kernel(const float* __restrict__ X,
                                                      const float* __restrict__ Wself,
                                                      const float* __restrict__ Wneigh,
                                                      const float* __restrict__ bias,
                                                      float* __restrict__ out) {
    __shared__ float AT[64 * 64];
    __shared__ float WS[64 * 64];
    __shared__ float BS[64];
    int tid = threadIdx.x;
    int row0 = blockIdx.x * 64;
    int tx4 = (tid & 15) * 4;
    int ty4 = (tid >> 4) * 4;

    const float* src = USE_H1 ? (const float*)g_H1 : X;

    // phase 1: src @ Wself
    load_tileT(AT, src, row0);
    load_W(WS, Wself);
    if (tid < 64) BS[tid] = bias[tid];
    __syncthreads();

    float4 c0 = make_float4(0.f, 0.f, 0.f, 0.f);
    float4 c1 = c0, c2 = c0, c3 = c0;
    GEMM_LOOP(AT, WS);
    __syncthreads();

    // phase 2: + AGG @ Wneigh
    load_tileT(AT, (const float*)g_AGG, row0);
    load_W(WS, Wneigh);
    __syncthreads();
    GEMM_LOOP(AT, WS);

    float bx = BS[tx4 + 0], by = BS[tx4 + 1], bz = BS[tx4 + 2], bw = BS[tx4 + 3];
    float* outp = OUT_IS_H1 ? (float*)g_H1 : out;
    STORE_ROW(c0, 0, outp);
    STORE_ROW(c1, 1, outp);
    STORE_ROW(c2, 2, outp);
    STORE_ROW(c3, 3, outp);
}

// ---------------- max-pool aggregation: half-warp per dst node -------------
__global__ __launch_bounds__(256) void aggregate_kernel() {
    int node = blockIdx.x * 16 + (threadIdx.x >> 4);
    if (node >= N_NODES) return;
    int l = threadIdx.x & 15;
    int beg = g_off[node];
    int end = g_off[node + 1];
    float4 m = make_float4(0.f, 0.f, 0.f, 0.f);  // relu >= 0 == DGL zero-fill
    int i = beg;
    for (; i + 1 < end; i += 2) {
        int s0 = g_csr[i];
        int s1 = g_csr[i + 1];
        float4 v0 = *reinterpret_cast<const float4*>(&g_P[s0 * D + l * 4]);
        float4 v1 = *reinterpret_cast<const float4*>(&g_P[s1 * D + l * 4]);
        m.x = fmaxf(m.x, fmaxf(v0.x, v1.x));
        m.y = fmaxf(m.y, fmaxf(v0.y, v1.y));
        m.z = fmaxf(m.z, fmaxf(v0.z, v1.z));
        m.w = fmaxf(m.w, fmaxf(v0.w, v1.w));
    }
    if (i < end) {
        int s = g_csr[i];
        float4 v = *reinterpret_cast<const float4*>(&g_P[s * D + l * 4]);
        m.x = fmaxf(m.x, v.x);
        m.y = fmaxf(m.y, v.y);
        m.z = fmaxf(m.z, v.z);
        m.w = fmaxf(m.w, v.w);
    }
    *reinterpret_cast<float4*>(&g_AGG[node * D + l * 4]) = m;
}

// ---------------- launch ----------------
extern "C" void kernel_launch(void* const* d_in, const int* in_sizes, int n_in,
                              void* d_out, int out_size) {
    const float* x    = (const float*)d_in[0];
    const int*   esrc = (const int*)d_in[1];
    const int*   edst = (const int*)d_in[2];
    const float* Wp1  = (const float*)d_in[3];
    const float* bp1  = (const float*)d_in[4];
    const float* Ws1  = (const float*)d_in[5];
    const float* Wn1  = (const float*)d_in[6];
    const float* b1   = (const float*)d_in[7];
    const float* Wp2  = (const float*)d_in[8];
    const float* bp2  = (const float*)d_in[9];
    const float* Ws2  = (const float*)d_in[10];
    const float* Wn2  = (const float*)d_in[11];
    const float* b2   = (const float*)d_in[12];
    float* out = (float*)d_out;

    int E = in_sizes[1];
    if (E > E_MAX) E = E_MAX;

    const int eb = (E + 255) / 256;
    const int nb_nodes = (N_NODES + 256) / 256;      // covers N_NODES+1
    const int gemm_blocks = (N_NODES + 63) / 64;
    const int agg_blocks = (N_NODES + 15) / 16;      // 16 nodes/block

    // CSR build (shared by both layers)
    zero_deg_kernel<<<nb_nodes, 256>>>();
    count_deg_kernel<<<eb, 256>>>(edst, E);
    scan_deg_kernel<<<1, 1024>>>();
    fill_csr_kernel<<<eb, 256>>>(esrc, edst, E);

    // layer 1
    fc_kernel<0, 0><<<gemm_blocks, 256>>>(x, Wp1, bp1);
    aggregate_kernel<<<agg_blocks, 256>>>();
    combine_kernel<1, 0, 1><<<gemm_blocks, 256>>>(x, Ws1, Wn1, b1, out);

    // layer 2
    fc_kernel<0, 1><<<gemm_blocks, 256>>>(x, Wp2, bp2);
    aggregate_kernel<<<agg_blocks, 256>>>();
    combine_kernel<2, 1, 0><<<gemm_blocks, 256>>>(x, Ws2, Wn2, b2, out);
}

// round 6
// speedup vs baseline: 2.0922x; 1.0437x over previous
#include <cuda_runtime.h>
#include <cuda_fp16.h>

#define N_NODES 100000
#define D 64
#define E_MAX 1600000

// ---------------- device scratch (no allocations allowed) ----------------
__device__ __half g_P[N_NODES * D];    // relu(fc_pool(h)) per node, fp16
__device__ __half g_AGG[N_NODES * D];  // max-pool aggregation, fp16
__device__ float  g_H1[N_NODES * D];   // layer-1 output, fp32
__device__ int    g_deg[N_NODES + 1];
__device__ int    g_off[N_NODES + 1];
__device__ int    g_cur[N_NODES];
__device__ int    g_csr[E_MAX];        // src node per edge, grouped by dst

// ---------------- CSR build ----------------
__global__ void zero_deg_kernel() {
    int i = blockIdx.x * blockDim.x + threadIdx.x;
    if (i <= N_NODES) g_deg[i] = 0;
}

__global__ void count_deg_kernel(const int* __restrict__ dst, int E) {
    int base = (blockIdx.x * blockDim.x + threadIdx.x) * 4;
    if (base + 3 < E) {
        int4 d = *reinterpret_cast<const int4*>(dst + base);
        atomicAdd(&g_deg[d.x], 1);
        atomicAdd(&g_deg[d.y], 1);
        atomicAdd(&g_deg[d.z], 1);
        atomicAdd(&g_deg[d.w], 1);
    } else {
        for (int i = base; i < E; i++) atomicAdd(&g_deg[dst[i]], 1);
    }
}

// single-block exclusive scan over 100001 entries; also seeds the cursor
__global__ void scan_deg_kernel() {
    __shared__ int sums[1024];
    int tid = threadIdx.x;
    const int chunk = (N_NODES + 1023) / 1024;
    int start = tid * chunk;
    int end = min(start + chunk, N_NODES);
    int s = 0;
    for (int i = start; i < end; i++) s += g_deg[i];
    sums[tid] = s;
    __syncthreads();
    for (int off = 1; off < 1024; off <<= 1) {
        int v = (tid >= off) ? sums[tid - off] : 0;
        __syncthreads();
        sums[tid] += v;
        __syncthreads();
    }
    int run = (tid > 0) ? sums[tid - 1] : 0;
    for (int i = start; i < end; i++) {
        g_off[i] = run;
        g_cur[i] = run;
        run += g_deg[i];
    }
    if (tid == 1023) g_off[N_NODES] = run;
}

__global__ void fill_csr_kernel(const int* __restrict__ src,
                                const int* __restrict__ dst, int E) {
    int base = (blockIdx.x * blockDim.x + threadIdx.x) * 4;
    if (base + 3 < E) {
        int4 d = *reinterpret_cast<const int4*>(dst + base);
        int4 s = *reinterpret_cast<const int4*>(src + base);
        int p0 = atomicAdd(&g_cur[d.x], 1);
        int p1 = atomicAdd(&g_cur[d.y], 1);
        int p2 = atomicAdd(&g_cur[d.z], 1);
        int p3 = atomicAdd(&g_cur[d.w], 1);
        g_csr[p0] = s.x;
        g_csr[p1] = s.y;
        g_csr[p2] = s.z;
        g_csr[p3] = s.w;
    } else {
        for (int i = base; i < E; i++) {
            int p = atomicAdd(&g_cur[dst[i]], 1);
            g_csr[p] = src[i];
        }
    }
}

// ---------------- register-tiled GEMM machinery ----------------
// Block: 256 threads, tile = 64 rows x 64 cols, thread = 4x4 micro-tile held
// in four named float4s. Device globals referenced ONLY from device code.

__device__ __forceinline__ void load_tileT(float* __restrict__ AT,
                                           const float* __restrict__ src,
                                           int row0) {
    int tid = threadIdx.x;
    #pragma unroll
    for (int i = 0; i < 4; i++) {
        int idx = i * 256 + tid;          // 0..1023 float4 slots
        int r = idx & 63;                  // row within tile
        int c4 = idx >> 6;                 // float4-column 0..15
        int gr = row0 + r;
        float4 v = make_float4(0.f, 0.f, 0.f, 0.f);
        if (gr < N_NODES) v = *reinterpret_cast<const float4*>(&src[gr * D + c4 * 4]);
        int k0 = c4 * 4;
        AT[(k0 + 0) * 64 + r] = v.x;
        AT[(k0 + 1) * 64 + r] = v.y;
        AT[(k0 + 2) * 64 + r] = v.z;
        AT[(k0 + 3) * 64 + r] = v.w;
    }
}

// half-precision source (g_AGG) -> fp32 k-major smem tile
__device__ __forceinline__ void load_tileT_half(float* __restrict__ AT,
                                                const __half* __restrict__ src,
                                                int row0) {
    int tid = threadIdx.x;
    #pragma unroll
    for (int i = 0; i < 4; i++) {
        int idx = i * 256 + tid;          // 0..1023 4-half slots
        int r = idx & 63;
        int c4 = idx >> 6;                 // 4-half column 0..15
        int gr = row0 + r;
        float f0 = 0.f, f1 = 0.f, f2 = 0.f, f3 = 0.f;
        if (gr < N_NODES) {
            uint2 a = *reinterpret_cast<const uint2*>(src + (size_t)gr * D + c4 * 4);
            __half2 h01 = *reinterpret_cast<__half2*>(&a.x);
            __half2 h23 = *reinterpret_cast<__half2*>(&a.y);
            float2 lo = __half22float2(h01);
            float2 hi = __half22float2(h23);
            f0 = lo.x; f1 = lo.y; f2 = hi.x; f3 = hi.y;
        }
        int k0 = c4 * 4;
        AT[(k0 + 0) * 64 + r] = f0;
        AT[(k0 + 1) * 64 + r] = f1;
        AT[(k0 + 2) * 64 + r] = f2;
        AT[(k0 + 3) * 64 + r] = f3;
    }
}

__device__ __forceinline__ void load_W(float* __restrict__ WS,
                                       const float* __restrict__ W) {
    int tid = threadIdx.x;
    float4* d = reinterpret_cast<float4*>(WS);
    const float4* s = reinterpret_cast<const float4*>(W);
    #pragma unroll
    for (int i = 0; i < 4; i++) d[i * 256 + tid] = s[i * 256 + tid];
}

// inner product loop over k: 2x LDS.128 feed 16 FMAs into named accumulators
#define GEMM_LOOP(ATbuf, WSbuf)                                                \
    _Pragma("unroll")                                                          \
    for (int k = 0; k < D; k++) {                                              \
        float4 a = *reinterpret_cast<const float4*>(&(ATbuf)[k * 64 + ty4]);   \
        float4 w = *reinterpret_cast<const float4*>(&(WSbuf)[k * 64 + tx4]);   \
        c0.x += a.x * w.x; c0.y += a.x * w.y; c0.z += a.x * w.z; c0.w += a.x * w.w; \
        c1.x += a.y * w.x; c1.y += a.y * w.y; c1.z += a.y * w.z; c1.w += a.y * w.w; \
        c2.x += a.z * w.x; c2.y += a.z * w.y; c2.z += a.z * w.z; c2.w += a.z * w.w; \
        c3.x += a.w * w.x; c3.y += a.w * w.y; c3.z += a.w * w.z; c3.w += a.w * w.w; \
    }

// relu + convert to fp16, store 4 halves (8B) into g_P
#define STORE_ROW_HALF(cr, roff)                                               \
    {                                                                          \
        int gr = row0 + ty4 + (roff);                                          \
        if (gr < N_NODES) {                                                    \
            float v0 = fmaxf(cr.x + bx, 0.f), v1 = fmaxf(cr.y + by, 0.f);      \
            float v2 = fmaxf(cr.z + bz, 0.f), v3 = fmaxf(cr.w + bw, 0.f);      \
            __half2 h01 = __floats2half2_rn(v0, v1);                           \
            __half2 h23 = __floats2half2_rn(v2, v3);                           \
            uint2 o;                                                           \
            o.x = *reinterpret_cast<unsigned*>(&h01);                          \
            o.y = *reinterpret_cast<unsigned*>(&h23);                          \
            *reinterpret_cast<uint2*>(&g_P[(size_t)gr * D + tx4]) = o;         \
        }                                                                      \
    }

// ACT: 1 = tanh, 2 = none; fp32 float4 store
#define STORE_ROW_F32(cr, roff, outp)                                          \
    {                                                                          \
        int gr = row0 + ty4 + (roff);                                          \
        if (gr < N_NODES) {                                                    \
            float v0 = cr.x + bx, v1 = cr.y + by, v2 = cr.z + bz, v3 = cr.w + bw; \
            if (ACT == 1) { v0 = tanhf(v0); v1 = tanhf(v1);                    \
                            v2 = tanhf(v2); v3 = tanhf(v3); }                  \
            float4 o; o.x = v0; o.y = v1; o.z = v2; o.w = v3;                  \
            *reinterpret_cast<float4*>(&(outp)[gr * D + tx4]) = o;             \
        }                                                                      \
    }

// P = relu(src @ W + b) -> g_P (fp16); src = X (layer 1) or g_H1 (layer 2)
template <int USE_H1>
__global__ __launch_bounds__(256) void fc_kernel(const float* __restrict__ X,
                                                 const float* __restrict__ W,
                                                 const float* __restrict__ b) {
    __shared__ float AT[64 * 64];
    __shared__ float WS[64 * 64];
    __shared__ float BS[64];
    int tid = threadIdx.x;
    int row0 = blockIdx.x * 64;
    int tx4 = (tid & 15) * 4;
    int ty4 = (tid >> 4) * 4;

    const float* src = USE_H1 ? (const float*)g_H1 : X;
    load_tileT(AT, src, row0);
    load_W(WS, W);
    if (tid < 64) BS[tid] = b[tid];
    __syncthreads();

    float4 c0 = make_float4(0.f, 0.f, 0.f, 0.f);
    float4 c1 = c0, c2 = c0, c3 = c0;
    GEMM_LOOP(AT, WS);

    float bx = BS[tx4 + 0], by = BS[tx4 + 1], bz = BS[tx4 + 2], bw = BS[tx4 + 3];
    STORE_ROW_HALF(c0, 0);
    STORE_ROW_HALF(c1, 1);
    STORE_ROW_HALF(c2, 2);
    STORE_ROW_HALF(c3, 3);
}

// out = act(src@Wself + AGG@Wneigh + bias); src/out selected by flags
template <int ACT, int USE_H1, int OUT_IS_H1>
__global__ __launch_bounds__(256) void combine_kernel(const float* __restrict__ X,
                                                      const float* __restrict__ Wself,
                                                      const float* __restrict__ Wneigh,
                                                      const float* __restrict__ bias,
                                                      float* __restrict__ out) {
    __shared__ float AT[64 * 64];
    __shared__ float WS[64 * 64];
    __shared__ float BS[64];
    int tid = threadIdx.x;
    int row0 = blockIdx.x * 64;
    int tx4 = (tid & 15) * 4;
    int ty4 = (tid >> 4) * 4;

    const float* src = USE_H1 ? (const float*)g_H1 : X;

    // phase 1: src @ Wself
    load_tileT(AT, src, row0);
    load_W(WS, Wself);
    if (tid < 64) BS[tid] = bias[tid];
    __syncthreads();

    float4 c0 = make_float4(0.f, 0.f, 0.f, 0.f);
    float4 c1 = c0, c2 = c0, c3 = c0;
    GEMM_LOOP(AT, WS);
    __syncthreads();

    // phase 2: + AGG @ Wneigh  (AGG is fp16)
    load_tileT_half(AT, (const __half*)g_AGG, row0);
    load_W(WS, Wneigh);
    __syncthreads();
    GEMM_LOOP(AT, WS);

    float bx = BS[tx4 + 0], by = BS[tx4 + 1], bz = BS[tx4 + 2], bw = BS[tx4 + 3];
    float* outp = OUT_IS_H1 ? (float*)g_H1 : out;
    STORE_ROW_F32(c0, 0, outp);
    STORE_ROW_F32(c1, 1, outp);
    STORE_ROW_F32(c2, 2, outp);
    STORE_ROW_F32(c3, 3, outp);
}

// ---------------- max-pool aggregation: half-warp per dst node -------------
// fp16 rows: 128B per edge row = 1 cache line; lane handles 4 halves (8B).
__global__ __launch_bounds__(256) void aggregate_kernel() {
    int node = blockIdx.x * 16 + (threadIdx.x >> 4);
    if (node >= N_NODES) return;
    int l = threadIdx.x & 15;
    int beg = g_off[node];
    int end = g_off[node + 1];
    __half2 m0 = __float2half2_rn(0.f);   // relu >= 0 == DGL zero-fill
    __half2 m1 = m0;
    int i = beg;
    for (; i + 1 < end; i += 2) {
        int s0 = g_csr[i];
        int s1 = g_csr[i + 1];
        uint2 a = *reinterpret_cast<const uint2*>(g_P + (size_t)s0 * D + l * 4);
        uint2 b = *reinterpret_cast<const uint2*>(g_P + (size_t)s1 * D + l * 4);
        m0 = __hmax2(m0, __hmax2(*reinterpret_cast<__half2*>(&a.x),
                                 *reinterpret_cast<__half2*>(&b.x)));
        m1 = __hmax2(m1, __hmax2(*reinterpret_cast<__half2*>(&a.y),
                                 *reinterpret_cast<__half2*>(&b.y)));
    }
    if (i < end) {
        int s = g_csr[i];
        uint2 a = *reinterpret_cast<const uint2*>(g_P + (size_t)s * D + l * 4);
        m0 = __hmax2(m0, *reinterpret_cast<__half2*>(&a.x));
        m1 = __hmax2(m1, *reinterpret_cast<__half2*>(&a.y));
    }
    uint2 o;
    o.x = *reinterpret_cast<unsigned*>(&m0);
    o.y = *reinterpret_cast<unsigned*>(&m1);
    *reinterpret_cast<uint2*>(g_AGG + (size_t)node * D + l * 4) = o;
}

// ---------------- launch ----------------
extern "C" void kernel_launch(void* const* d_in, const int* in_sizes, int n_in,
                              void* d_out, int out_size) {
    const float* x    = (const float*)d_in[0];
    const int*   esrc = (const int*)d_in[1];
    const int*   edst = (const int*)d_in[2];
    const float* Wp1  = (const float*)d_in[3];
    const float* bp1  = (const float*)d_in[4];
    const float* Ws1  = (const float*)d_in[5];
    const float* Wn1  = (const float*)d_in[6];
    const float* b1   = (const float*)d_in[7];
    const float* Wp2  = (const float*)d_in[8];
    const float* bp2  = (const float*)d_in[9];
    const float* Ws2  = (const float*)d_in[10];
    const float* Wn2  = (const float*)d_in[11];
    const float* b2   = (const float*)d_in[12];
    float* out = (float*)d_out;

    int E = in_sizes[1];
    if (E > E_MAX) E = E_MAX;

    const int eb4 = ((E + 3) / 4 + 255) / 256;       // 4 edges per thread
    const int nb_nodes = (N_NODES + 256) / 256;      // covers N_NODES+1
    const int gemm_blocks = (N_NODES + 63) / 64;
    const int agg_blocks = (N_NODES + 15) / 16;      // 16 nodes/block

    // CSR build (shared by both layers)
    zero_deg_kernel<<<nb_nodes, 256>>>();
    count_deg_kernel<<<eb4, 256>>>(edst, E);
    scan_deg_kernel<<<1, 1024>>>();
    fill_csr_kernel<<<eb4, 256>>>(esrc, edst, E);

    // layer 1
    fc_kernel<0><<<gemm_blocks, 256>>>(x, Wp1, bp1);
    aggregate_kernel<<<agg_blocks, 256>>>();
    combine_kernel<1, 0, 1><<<gemm_blocks, 256>>>(x, Ws1, Wn1, b1, out);

    // layer 2
    fc_kernel<1><<<gemm_blocks, 256>>>(x, Wp2, bp2);
    aggregate_kernel<<<agg_blocks, 256>>>();
    combine_kernel<2, 1, 0><<<gemm_blocks, 256>>>(x, Ws2, Wn2, b2, out);
}

// round 8
// speedup vs baseline: 2.8757x; 1.3745x over previous
#include <cuda_runtime.h>
#include <cuda_fp16.h>

#define N_NODES 100000
#define D 64
#define E_MAX 1600000
#define LDA 72   // smem tile leading dim (halves); 144B rows, conflict-free ldmatrix

// ---------------- device scratch (no allocations allowed) ----------------
__device__ __half g_P[N_NODES * D];    // relu(fc_pool(h)) per node, fp16
__device__ __half g_AGG[N_NODES * D];  // max-pool aggregation, fp16
__device__ float  g_H1[N_NODES * D];   // layer-1 output, fp32
__device__ int    g_deg[N_NODES + 1];
__device__ int    g_off[N_NODES + 1];
__device__ int    g_cur[N_NODES];
__device__ int    g_csr[E_MAX];        // src node per edge, grouped by dst

// ---------------- CSR build ----------------
__global__ void zero_deg_kernel() {
    int i = blockIdx.x * blockDim.x + threadIdx.x;
    if (i <= N_NODES) g_deg[i] = 0;
}

__global__ void count_deg_kernel(const int* __restrict__ dst, int E) {
    int base = (blockIdx.x * blockDim.x + threadIdx.x) * 4;
    if (base + 3 < E) {
        int4 d = *reinterpret_cast<const int4*>(dst + base);
        atomicAdd(&g_deg[d.x], 1);
        atomicAdd(&g_deg[d.y], 1);
        atomicAdd(&g_deg[d.z], 1);
        atomicAdd(&g_deg[d.w], 1);
    } else {
        for (int i = base; i < E; i++) atomicAdd(&g_deg[dst[i]], 1);
    }
}

__global__ void scan_deg_kernel() {
    __shared__ int sums[1024];
    int tid = threadIdx.x;
    const int chunk = (N_NODES + 1023) / 1024;
    int start = tid * chunk;
    int end = min(start + chunk, N_NODES);
    int s = 0;
    for (int i = start; i < end; i++) s += g_deg[i];
    sums[tid] = s;
    __syncthreads();
    for (int off = 1; off < 1024; off <<= 1) {
        int v = (tid >= off) ? sums[tid - off] : 0;
        __syncthreads();
        sums[tid] += v;
        __syncthreads();
    }
    int run = (tid > 0) ? sums[tid - 1] : 0;
    for (int i = start; i < end; i++) {
        g_off[i] = run;
        g_cur[i] = run;
        run += g_deg[i];
    }
    if (tid == 1023) g_off[N_NODES] = run;
}

__global__ void fill_csr_kernel(const int* __restrict__ src,
                                const int* __restrict__ dst, int E) {
    int base = (blockIdx.x * blockDim.x + threadIdx.x) * 4;
    if (base + 3 < E) {
        int4 d = *reinterpret_cast<const int4*>(dst + base);
        int4 s = *reinterpret_cast<const int4*>(src + base);
        int p0 = atomicAdd(&g_cur[d.x], 1);
        int p1 = atomicAdd(&g_cur[d.y], 1);
        int p2 = atomicAdd(&g_cur[d.z], 1);
        int p3 = atomicAdd(&g_cur[d.w], 1);
        g_csr[p0] = s.x;
        g_csr[p1] = s.y;
        g_csr[p2] = s.z;
        g_csr[p3] = s.w;
    } else {
        for (int i = base; i < E; i++) {
            int p = atomicAdd(&g_cur[dst[i]], 1);
            g_csr[p] = src[i];
        }
    }
}

// ---------------- tensor-core GEMM machinery ----------------
// Block = 128 threads (4 warps); tile = 64 rows x 64 cols; warp owns 16x64.
// A: row-major fp16 smem tile (ld=72); B: k-major fp16 smem tile (ld=72).
// mma.sync.m16n8k16 f16 -> f32 accumulate.

__device__ __forceinline__ unsigned smem_u32(const void* p) {
    return (unsigned)__cvta_generic_to_shared(p);
}

__device__ __forceinline__ void ldsm_x4(unsigned& r0, unsigned& r1,
                                        unsigned& r2, unsigned& r3, unsigned a) {
    asm volatile("ldmatrix.sync.aligned.m8n8.x4.shared.b16 {%0,%1,%2,%3},[%4];"
                 : "=r"(r0), "=r"(r1), "=r"(r2), "=r"(r3) : "r"(a));
}

__device__ __forceinline__ void ldsm_x4t(unsigned& r0, unsigned& r1,
                                         unsigned& r2, unsigned& r3, unsigned a) {
    asm volatile("ldmatrix.sync.aligned.m8n8.x4.trans.shared.b16 {%0,%1,%2,%3},[%4];"
                 : "=r"(r0), "=r"(r1), "=r"(r2), "=r"(r3) : "r"(a));
}

__device__ __forceinline__ void mma_16816(float4& c, unsigned a0, unsigned a1,
                                          unsigned a2, unsigned a3,
                                          unsigned b0, unsigned b1) {
    asm volatile(
        "mma.sync.aligned.m16n8k16.row.col.f32.f16.f16.f32 "
        "{%0,%1,%2,%3},{%4,%5,%6,%7},{%8,%9},{%0,%1,%2,%3};"
        : "+f"(c.x), "+f"(c.y), "+f"(c.z), "+f"(c.w)
        : "r"(a0), "r"(a1), "r"(a2), "r"(a3), "r"(b0), "r"(b1));
}

// fp32 source -> fp16 row-major tile
__device__ __forceinline__ void load_tileA_f32(__half* __restrict__ As,
                                               const float* __restrict__ src,
                                               int row0) {
    int tid = threadIdx.x;  // 128
    #pragma unroll
    for (int i = 0; i < 8; i++) {
        int idx = i * 128 + tid;       // 1024 float4 slots
        int r = idx >> 4, c4 = idx & 15;
        int gr = row0 + r;
        float4 v = make_float4(0.f, 0.f, 0.f, 0.f);
        if (gr < N_NODES) v = *reinterpret_cast<const float4*>(&src[(size_t)gr * D + c4 * 4]);
        __half2 h01 = __floats2half2_rn(v.x, v.y);
        __half2 h23 = __floats2half2_rn(v.z, v.w);
        uint2 o;
        o.x = *reinterpret_cast<unsigned*>(&h01);
        o.y = *reinterpret_cast<unsigned*>(&h23);
        *reinterpret_cast<uint2*>(&As[r * LDA + c4 * 4]) = o;
    }
}

// fp16 source (g_AGG) -> fp16 row-major tile (straight copy)
// uint2 = 4 halves; 64 halves/row = 16 chunks; 64 rows * 16 = 1024 slots.
__device__ __forceinline__ void load_tileA_h(__half* __restrict__ As,
                                             const __half* __restrict__ src,
                                             int row0) {
    int tid = threadIdx.x;
    #pragma unroll
    for (int i = 0; i < 8; i++) {
        int idx = i * 128 + tid;       // 1024 uint2 slots
        int r = idx >> 4, c4 = idx & 15;
        int gr = row0 + r;
        uint2 o = make_uint2(0u, 0u);
        if (gr < N_NODES) o = *reinterpret_cast<const uint2*>(&src[(size_t)gr * D + c4 * 4]);
        *reinterpret_cast<uint2*>(&As[r * LDA + c4 * 4]) = o;
    }
}

// fp32 weight [64][64] -> fp16 k-major tile
__device__ __forceinline__ void load_tileB_f32(__half* __restrict__ Bs,
                                               const float* __restrict__ W) {
    int tid = threadIdx.x;
    #pragma unroll
    for (int i = 0; i < 8; i++) {
        int idx = i * 128 + tid;
        int r = idx >> 4, c4 = idx & 15;
        float4 v = *reinterpret_cast<const float4*>(&W[r * D + c4 * 4]);
        __half2 h01 = __floats2half2_rn(v.x, v.y);
        __half2 h23 = __floats2half2_rn(v.z, v.w);
        uint2 o;
        o.x = *reinterpret_cast<unsigned*>(&h01);
        o.y = *reinterpret_cast<unsigned*>(&h23);
        *reinterpret_cast<uint2*>(&Bs[r * LDA + c4 * 4]) = o;
    }
}

// accumulate 16x64 per warp into C0..C7 (each float4 = one m16n8 fragment)
#define TC_GEMM(AsP, BsP)                                                       \
    do {                                                                        \
        unsigned abase = smem_u32(&(AsP)[(wr + (lane & 15)) * LDA + ((lane >> 4) << 3)]); \
        int kl = lane & 15;                                                     \
        int ng = ((lane >> 4) & 1) << 3;                                        \
        _Pragma("unroll")                                                       \
        for (int k0 = 0; k0 < 64; k0 += 16) {                                   \
            unsigned a0, a1, a2, a3, b0, b1, b2, b3, ba;                        \
            ldsm_x4(a0, a1, a2, a3, abase + k0 * 2);                            \
            ba = smem_u32(&(BsP)[(k0 + kl) * LDA + 0 + ng]);                    \
            ldsm_x4t(b0, b1, b2, b3, ba);                                       \
            mma_16816(C0, a0, a1, a2, a3, b0, b1);                              \
            mma_16816(C1, a0, a1, a2, a3, b2, b3);                              \
            ba = smem_u32(&(BsP)[(k0 + kl) * LDA + 16 + ng]);                   \
            ldsm_x4t(b0, b1, b2, b3, ba);                                       \
            mma_16816(C2, a0, a1, a2, a3, b0, b1);                              \
            mma_16816(C3, a0, a1, a2, a3, b2, b3);                              \
            ba = smem_u32(&(BsP)[(k0 + kl) * LDA + 32 + ng]);                   \
            ldsm_x4t(b0, b1, b2, b3, ba);                                       \
            mma_16816(C4, a0, a1, a2, a3, b0, b1);                              \
            mma_16816(C5, a0, a1, a2, a3, b2, b3);                              \
            ba = smem_u32(&(BsP)[(k0 + kl) * LDA + 48 + ng]);                   \
            ldsm_x4t(b0, b1, b2, b3, ba);                                       \
            mma_16816(C6, a0, a1, a2, a3, b0, b1);                              \
            mma_16816(C7, a0, a1, a2, a3, b2, b3);                              \
        }                                                                       \
    } while (0)

// epilogue: fragment (g,tig) maps to rows (wr+g, wr+g+8), cols (t*8+2tig, +1)
#define FC_STORE(Ct, t)                                                         \
    {                                                                           \
        int n = (t) * 8 + 2 * tig;                                              \
        int ra = row0 + wr + g;                                                 \
        if (ra < N_NODES) {                                                     \
            __half2 h = __floats2half2_rn(fmaxf(Ct.x + BSs[n], 0.f),            \
                                          fmaxf(Ct.y + BSs[n + 1], 0.f));       \
            *reinterpret_cast<unsigned*>(&g_P[(size_t)ra * D + n]) =            \
                *reinterpret_cast<unsigned*>(&h);                               \
        }                                                                       \
        int rb = ra + 8;                                                        \
        if (rb < N_NODES) {                                                     \
            __half2 h = __floats2half2_rn(fmaxf(Ct.z + BSs[n], 0.f),            \
                                          fmaxf(Ct.w + BSs[n + 1], 0.f));       \
            *reinterpret_cast<unsigned*>(&g_P[(size_t)rb * D + n]) =            \
                *reinterpret_cast<unsigned*>(&h);                               \
        }                                                                       \
    }

#define CB_STORE(Ct, t)                                                         \
    {                                                                           \
        int n = (t) * 8 + 2 * tig;                                              \
        int ra = row0 + wr + g;                                                 \
        if (ra < N_NODES) {                                                     \
            float vx = Ct.x + BSs[n], vy = Ct.y + BSs[n + 1];                    \
            if (ACT == 1) { vx = tanhf(vx); vy = tanhf(vy); }                   \
            float2 o; o.x = vx; o.y = vy;                                       \
            *reinterpret_cast<float2*>(&outp[(size_t)ra * D + n]) = o;          \
        }                                                                       \
        int rb = ra + 8;                                                        \
        if (rb < N_NODES) {                                                     \
            float vx = Ct.z + BSs[n], vy = Ct.w + BSs[n + 1];                    \
            if (ACT == 1) { vx = tanhf(vx); vy = tanhf(vy); }                   \
            float2 o; o.x = vx; o.y = vy;                                       \
            *reinterpret_cast<float2*>(&outp[(size_t)rb * D + n]) = o;          \
        }                                                                       \
    }

// P = relu(src @ W + b) -> g_P (fp16); src = X (layer 1) or g_H1 (layer 2)
template <int USE_H1>
__global__ __launch_bounds__(128) void fc_tc_kernel(const float* __restrict__ X,
                                                    const float* __restrict__ W,
                                                    const float* __restrict__ b) {
    __shared__ alignas(16) __half As[64 * LDA];
    __shared__ alignas(16) __half Bs[64 * LDA];
    __shared__ float BSs[64];
    int tid = threadIdx.x;
    int lane = tid & 31;
    int wr = (tid >> 5) * 16;
    int g = lane >> 2, tig = lane & 3;
    int row0 = blockIdx.x * 64;

    const float* src = USE_H1 ? (const float*)g_H1 : X;
    load_tileA_f32(As, src, row0);
    load_tileB_f32(Bs, W);
    if (tid < 64) BSs[tid] = b[tid];
    __syncthreads();

    float4 C0 = make_float4(0.f, 0.f, 0.f, 0.f);
    float4 C1 = C0, C2 = C0, C3 = C0, C4 = C0, C5 = C0, C6 = C0, C7 = C0;
    TC_GEMM(As, Bs);

    FC_STORE(C0, 0); FC_STORE(C1, 1); FC_STORE(C2, 2); FC_STORE(C3, 3);
    FC_STORE(C4, 4); FC_STORE(C5, 5); FC_STORE(C6, 6); FC_STORE(C7, 7);
}

// out = act(src@Wself + AGG@Wneigh + bias)
template <int ACT, int USE_H1, int OUT_IS_H1>
__global__ __launch_bounds__(128) void combine_tc_kernel(const float* __restrict__ X,
                                                         const float* __restrict__ Wself,
                                                         const float* __restrict__ Wneigh,
                                                         const float* __restrict__ bias,
                                                         float* __restrict__ out) {
    __shared__ alignas(16) __half As[64 * LDA];
    __shared__ alignas(16) __half Bs[64 * LDA];
    __shared__ float BSs[64];
    int tid = threadIdx.x;
    int lane = tid & 31;
    int wr = (tid >> 5) * 16;
    int g = lane >> 2, tig = lane & 3;
    int row0 = blockIdx.x * 64;

    const float* src = USE_H1 ? (const float*)g_H1 : X;

    // phase 1: src @ Wself
    load_tileA_f32(As, src, row0);
    load_tileB_f32(Bs, Wself);
    if (tid < 64) BSs[tid] = bias[tid];
    __syncthreads();

    float4 C0 = make_float4(0.f, 0.f, 0.f, 0.f);
    float4 C1 = C0, C2 = C0, C3 = C0, C4 = C0, C5 = C0, C6 = C0, C7 = C0;
    TC_GEMM(As, Bs);
    __syncthreads();

    // phase 2: + AGG @ Wneigh  (AGG already fp16)
    load_tileA_h(As, (const __half*)g_AGG, row0);
    load_tileB_f32(Bs, Wneigh);
    __syncthreads();
    TC_GEMM(As, Bs);

    float* outp = OUT_IS_H1 ? (float*)g_H1 : out;
    CB_STORE(C0, 0); CB_STORE(C1, 1); CB_STORE(C2, 2); CB_STORE(C3, 3);
    CB_STORE(C4, 4); CB_STORE(C5, 5); CB_STORE(C6, 6); CB_STORE(C7, 7);
}

// ---------------- max-pool aggregation: half-warp per dst node -------------
__global__ __launch_bounds__(256) void aggregate_kernel() {
    int node = blockIdx.x * 16 + (threadIdx.x >> 4);
    if (node >= N_NODES) return;
    int l = threadIdx.x & 15;
    int beg = g_off[node];
    int end = g_off[node + 1];
    __half2 m0 = __float2half2_rn(0.f);   // relu >= 0 == DGL zero-fill
    __half2 m1 = m0;
    int i = beg;
    for (; i + 1 < end; i += 2) {
        int s0 = g_csr[i];
        int s1 = g_csr[i + 1];
        uint2 a = *reinterpret_cast<const uint2*>(g_P + (size_t)s0 * D + l * 4);
        uint2 b = *reinterpret_cast<const uint2*>(g_P + (size_t)s1 * D + l * 4);
        m0 = __hmax2(m0, __hmax2(*reinterpret_cast<__half2*>(&a.x),
                                 *reinterpret_cast<__half2*>(&b.x)));
        m1 = __hmax2(m1, __hmax2(*reinterpret_cast<__half2*>(&a.y),
                                 *reinterpret_cast<__half2*>(&b.y)));
    }
    if (i < end) {
        int s = g_csr[i];
        uint2 a = *reinterpret_cast<const uint2*>(g_P + (size_t)s * D + l * 4);
        m0 = __hmax2(m0, *reinterpret_cast<__half2*>(&a.x));
        m1 = __hmax2(m1, *reinterpret_cast<__half2*>(&a.y));
    }
    uint2 o;
    o.x = *reinterpret_cast<unsigned*>(&m0);
    o.y = *reinterpret_cast<unsigned*>(&m1);
    *reinterpret_cast<uint2*>(g_AGG + (size_t)node * D + l * 4) = o;
}

// ---------------- launch ----------------
extern "C" void kernel_launch(void* const* d_in, const int* in_sizes, int n_in,
                              void* d_out, int out_size) {
    const float* x    = (const float*)d_in[0];
    const int*   esrc = (const int*)d_in[1];
    const int*   edst = (const int*)d_in[2];
    const float* Wp1  = (const float*)d_in[3];
    const float* bp1  = (const float*)d_in[4];
    const float* Ws1  = (const float*)d_in[5];
    const float* Wn1  = (const float*)d_in[6];
    const float* b1   = (const float*)d_in[7];
    const float* Wp2  = (const float*)d_in[8];
    const float* bp2  = (const float*)d_in[9];
    const float* Ws2  = (const float*)d_in[10];
    const float* Wn2  = (const float*)d_in[11];
    const float* b2   = (const float*)d_in[12];
    float* out = (float*)d_out;

    int E = in_sizes[1];
    if (E > E_MAX) E = E_MAX;

    const int eb4 = ((E + 3) / 4 + 255) / 256;       // 4 edges per thread
    const int nb_nodes = (N_NODES + 256) / 256;      // covers N_NODES+1
    const int gemm_blocks = (N_NODES + 63) / 64;
    const int agg_blocks = (N_NODES + 15) / 16;      // 16 nodes/block

    // CSR build (shared by both layers)
    zero_deg_kernel<<<nb_nodes, 256>>>();
    count_deg_kernel<<<eb4, 256>>>(edst, E);
    scan_deg_kernel<<<1, 1024>>>();
    fill_csr_kernel<<<eb4, 256>>>(esrc, edst, E);

    // layer 1
    fc_tc_kernel<0><<<gemm_blocks, 128>>>(x, Wp1, bp1);
    aggregate_kernel<<<agg_blocks, 256>>>();
    combine_tc_kernel<1, 0, 1><<<gemm_blocks, 128>>>(x, Ws1, Wn1, b1, out);

    // layer 2
    fc_tc_kernel<1><<<gemm_blocks, 128>>>(x, Wp2, bp2);
    aggregate_kernel<<<agg_blocks, 256>>>();
    combine_tc_kernel<2, 1, 0><<<gemm_blocks, 128>>>(x, Ws2, Wn2, b2, out);
}